// round 7
// baseline (speedup 1.0000x reference)
#include <cuda_runtime.h>
#include <cuda_bf16.h>
#include <math.h>
#include <stdint.h>

#define BN_    4
#define LL     2048
#define DMODEL 512
#define DI     1024
#define DI2    2048
#define DST    16
#define DTR    64
#define XD     96
#define NTOK   8192   // B * L

// tcgen05 only exists on the arch-specific target (sm_103a / sm_100a).
#if defined(__CUDA_ARCH_FEAT_SM103_ALL) || defined(__CUDA_ARCH_FEAT_SM100_ALL)
#define HAS_TC5 1
#endif

typedef __nv_bfloat16 bf16;

// ---------------- scratch (device globals: no allocation allowed) ----------------
// fp32 intermediates (single-buffered where consumed within one direction-iter)
__device__ float g_xp  [(size_t)NTOK * DI2];      // 64 MB
__device__ float g_xz  [(size_t)NTOK * DI2];      // 64 MB (per-iter)
__device__ float g_xma [(size_t)NTOK * DI];       // 32 MB (per-iter, scan u)
__device__ float g_xdbl[(size_t)NTOK * XD];       // 3 MB  (per-iter)
__device__ float g_dt  [(size_t)NTOK * DI];       // 32 MB (per-iter)
__device__ float g_mo  [2][(size_t)NTOK * DI];    // 64 MB
// bf16 hi/lo pre-split GEMM operands
__device__ bf16 g_xnh[(size_t)NTOK * DMODEL], g_xnl[(size_t)NTOK * DMODEL];
__device__ bf16 g_xah[(size_t)NTOK * DI],     g_xal[(size_t)NTOK * DI];
__device__ bf16 g_xmh[(size_t)NTOK * DI],     g_xml[(size_t)NTOK * DI];
__device__ bf16 g_xdh[(size_t)NTOK * XD],     g_xdl[(size_t)NTOK * XD];
__device__ bf16 g_ygh[(size_t)NTOK * DI],     g_ygl[(size_t)NTOK * DI];
__device__ bf16 g_ymh[(size_t)NTOK * DI2],    g_yml[(size_t)NTOK * DI2];
// weight split scratch (reused sequentially; max weight = 2M elems)
__device__ bf16 g_wh[(size_t)2 * 1024 * 1024], g_wl[(size_t)2 * 1024 * 1024];

__device__ __forceinline__ float siluf(float x)     { return x / (1.f + __expf(-x)); }
__device__ __forceinline__ float softplusf(float x) { return x > 20.f ? x : log1pf(__expf(x)); }

__device__ __forceinline__ uint32_t pack_bf16x2(float x, float y) {
    uint32_t r;
    asm("cvt.rn.bf16x2.f32 %0, %1, %2;" : "=r"(r) : "f"(y), "f"(x));  // {lo=x, hi=y}
    return r;
}
// split (x,y) into bf16 hi pair h and residual lo pair l
__device__ __forceinline__ void split2(float x, float y, uint32_t& h, uint32_t& l) {
    h = pack_bf16x2(x, y);
    const float rx = __uint_as_float(h << 16);
    const float ry = __uint_as_float(h & 0xffff0000u);
    l = pack_bf16x2(x - rx, y - ry);
}

// ---------------- weight split: fp32[n] -> hi/lo bf16 ----------------
__global__ void split_kernel(const float* __restrict__ in, bf16* __restrict__ hi,
                             bf16* __restrict__ lo, int n4)
{
    const int i = blockIdx.x * 256 + threadIdx.x;
    if (i < n4) {
        const float4 v = ((const float4*)in)[i];
        uint32_t h0, l0, h1, l1;
        split2(v.x, v.y, h0, l0);
        split2(v.z, v.w, h1, l1);
        ((uint2*)hi)[i] = make_uint2(h0, h1);
        ((uint2*)lo)[i] = make_uint2(l0, l1);
    }
}

// ---------------- LayerNorm -> split bf16 ----------------
__global__ void ln_kernel(const float* __restrict__ x, const float* __restrict__ gg,
                          const float* __restrict__ bb,
                          bf16* __restrict__ hi, bf16* __restrict__ lo)
{
    __shared__ float red[8];
    const int row = blockIdx.x;
    const int t   = threadIdx.x;
    float4 v = ((const float4*)(x + (size_t)row * DMODEL))[t];
    float s = v.x + v.y + v.z + v.w;
#pragma unroll
    for (int o = 16; o; o >>= 1) s += __shfl_xor_sync(0xffffffffu, s, o);
    if ((t & 31) == 0) red[t >> 5] = s;
    __syncthreads();
    const float mu = (red[0] + red[1] + red[2] + red[3]) * (1.f / DMODEL);
    const float dx = v.x - mu, dy = v.y - mu, dz = v.z - mu, dw = v.w - mu;
    float vs = dx*dx + dy*dy + dz*dz + dw*dw;
#pragma unroll
    for (int o = 16; o; o >>= 1) vs += __shfl_xor_sync(0xffffffffu, vs, o);
    if ((t & 31) == 0) red[4 + (t >> 5)] = vs;
    __syncthreads();
    const float var = (red[4] + red[5] + red[6] + red[7]) * (1.f / DMODEL);
    const float inv = rsqrtf(var + 1e-5f);
    const int i0 = t << 2;
    float ox = dx * inv * gg[i0+0] + bb[i0+0];
    float oy = dy * inv * gg[i0+1] + bb[i0+1];
    float oz = dz * inv * gg[i0+2] + bb[i0+2];
    float ow = dw * inv * gg[i0+3] + bb[i0+3];
    uint32_t h0, l0, h1, l1;
    split2(ox, oy, h0, l0);
    split2(oz, ow, h1, l1);
    ((uint2*)(hi + (size_t)row * DMODEL))[t] = make_uint2(h0, h1);
    ((uint2*)(lo + (size_t)row * DMODEL))[t] = make_uint2(l0, l1);
}

#ifdef HAS_TC5
// ---------------- tcgen05 helpers ----------------
__device__ __forceinline__ uint32_t smem_u32(const void* p) {
    uint32_t a;
    asm("{ .reg .u64 t; cvta.to.shared.u64 t, %1; cvt.u32.u64 %0, t; }" : "=r"(a) : "l"(p));
    return a;
}
__device__ __forceinline__ uint32_t elect1() {
    uint32_t p;
    asm volatile("{\n\t.reg .pred p;\n\telect.sync _|p, 0xFFFFFFFF;\n\tselp.b32 %0, 1, 0, p;\n\t}"
                 : "=r"(p));
    return p;
}
__device__ __forceinline__ uint32_t swz(uint32_t off) { return off ^ ((off >> 3) & 0x70); }

// SW128 K-major smem descriptor (Blackwell): layout=2, version=1, SBO=64, LBO=1
static __device__ __forceinline__ uint64_t mkdesc(uint32_t addr) {
    const uint64_t base = (2ull << 61) | (1ull << 46) | (64ull << 32) | (1ull << 16);
    return base | ((addr >> 4) & 0x3FFFu);
}

__device__ __forceinline__ void mma_f16_ss(uint32_t d, uint64_t a, uint64_t b,
                                           uint32_t idesc, uint32_t en) {
    asm volatile(
        "{\n\t.reg .pred p;\n\tsetp.ne.u32 p, %4, 0;\n\t"
        "tcgen05.mma.cta_group::1.kind::f16 [%0], %1, %2, %3, {%5,%5,%5,%5}, p;\n\t}"
        :: "r"(d), "l"(a), "l"(b), "r"(idesc), "r"(en), "r"(0u) : "memory");
}

__device__ __forceinline__ void mbar_wait(uint32_t mbar, uint32_t parity) {
    asm volatile(
        "{\n\t.reg .pred P;\n\t"
        "W_%=:\n\t"
        "mbarrier.try_wait.parity.acquire.cta.shared::cta.b64 P, [%0], %1, 0x989680;\n\t"
        "@P bra.uni D_%=;\n\t"
        "bra.uni W_%=;\n\t"
        "D_%=:\n\t}"
        :: "r"(mbar), "r"(parity) : "memory");
}

#define TC_LD32(r, addr) \
    asm volatile( \
        "tcgen05.ld.sync.aligned.32x32b.x32.b32 " \
        "{%0, %1, %2, %3, %4, %5, %6, %7, " \
        " %8, %9, %10, %11, %12, %13, %14, %15, " \
        " %16, %17, %18, %19, %20, %21, %22, %23, " \
        " %24, %25, %26, %27, %28, %29, %30, %31}, [%32];" \
        : "=r"((r)[0]),  "=r"((r)[1]),  "=r"((r)[2]),  "=r"((r)[3]), \
          "=r"((r)[4]),  "=r"((r)[5]),  "=r"((r)[6]),  "=r"((r)[7]), \
          "=r"((r)[8]),  "=r"((r)[9]),  "=r"((r)[10]), "=r"((r)[11]), \
          "=r"((r)[12]), "=r"((r)[13]), "=r"((r)[14]), "=r"((r)[15]), \
          "=r"((r)[16]), "=r"((r)[17]), "=r"((r)[18]), "=r"((r)[19]), \
          "=r"((r)[20]), "=r"((r)[21]), "=r"((r)[22]), "=r"((r)[23]), \
          "=r"((r)[24]), "=r"((r)[25]), "=r"((r)[26]), "=r"((r)[27]), \
          "=r"((r)[28]), "=r"((r)[29]), "=r"((r)[30]), "=r"((r)[31]) \
        : "r"(addr))
#else
__device__ __forceinline__ void mma_bf16(float* c, const uint32_t* a, const uint32_t* b) {
    asm volatile("mma.sync.aligned.m16n8k16.row.col.f32.bf16.bf16.f32 "
        "{%0,%1,%2,%3}, {%4,%5,%6,%7}, {%8,%9}, {%0,%1,%2,%3};"
        : "+f"(c[0]), "+f"(c[1]), "+f"(c[2]), "+f"(c[3])
        : "r"(a[0]), "r"(a[1]), "r"(a[2]), "r"(a[3]), "r"(b[0]), "r"(b[1]));
}
#endif

// ---------------- GEMM: C[M,N] = (Ah+Al)[M,K] @ (Wh+Wl)[N,K]^T, 3-pass split -------
// Pre-split bf16 inputs. M mult of 128, K mult of 64, N mult of 4 (tile zero-padded).
// EPI: 0 none, 1 softplus(acc+aux[n]), 2 acc+aux[m*N+n], 3 fp32 C + split (Ch,Cl).
#define SM_STAGE 65536          // 4 tiles x 16KB
#define SM_TOT   (1024 + 2 * SM_STAGE)

template<int EPI>
__global__ void __launch_bounds__(128)
gemm5(const bf16* __restrict__ Ah, const bf16* __restrict__ Al, int lda,
      const bf16* __restrict__ Wh, const bf16* __restrict__ Wl,
      float* __restrict__ C, int N, int K, const float* __restrict__ aux,
      bf16* __restrict__ Ch, bf16* __restrict__ Cl)
{
#ifdef HAS_TC5
    // ================= tcgen05 path (sm_103a SASS), double-buffered =================
    extern __shared__ __align__(1024) char sm[];
    const uint32_t sb = smem_u32(sm);
    const int tid = threadIdx.x, warp = tid >> 5, lane = tid & 31;
    const int m0 = blockIdx.y << 7, n0 = blockIdx.x << 7;

    if (warp == 0) {
        asm volatile("tcgen05.alloc.cta_group::1.sync.aligned.shared::cta.b32 [%0], %1;"
                     :: "r"(sb), "r"(128u) : "memory");
        asm volatile("tcgen05.relinquish_alloc_permit.cta_group::1.sync.aligned;");
    }
    if (tid == 0) {
        asm volatile("mbarrier.init.shared.b64 [%0], %1;" :: "r"(sb + 8),  "r"(1u) : "memory");
        asm volatile("mbarrier.init.shared.b64 [%0], %1;" :: "r"(sb + 16), "r"(1u) : "memory");
    }
    __syncthreads();
    uint32_t tmem;
    asm volatile("ld.shared.b32 %0, [%1];" : "=r"(tmem) : "r"(sb));

    const uint32_t idesc = 0x8200490u;   // M=128, N=128, bf16 x bf16 -> f32
    const int nsteps = K >> 6;
    uint32_t ph0 = 0, ph1 = 0;

    for (int s = 0; s < nsteps; s++) {
        const int st = s & 1;
        const uint32_t stb = 1024 + st * SM_STAGE;
        const int k0 = s << 6;
        if (s >= 2) {          // stage reused: wait for MMA of step s-2 to finish reading
            if (st == 0) { mbar_wait(sb + 8,  ph0); ph0 ^= 1; }
            else         { mbar_wait(sb + 16, ph1); ph1 ^= 1; }
        }
        // fill stage: pure bf16 copies into SW128-swizzled tiles
#pragma unroll
        for (int i = 0; i < 8; i++) {
            const int idx = tid + (i << 7);          // 0..1023
            const int r   = idx >> 3;                // row 0..127
            const int ch  = idx & 7;                 // 16B chunk (8 bf16)
            const uint32_t sw = swz((uint32_t)(r * 128 + ch * 16));
            const size_t aoff = (size_t)(m0 + r) * lda + k0 + (ch << 3);
            *(uint4*)(sm + stb + 0     + sw) = *(const uint4*)(Ah + aoff);
            *(uint4*)(sm + stb + 16384 + sw) = *(const uint4*)(Al + aoff);
            uint4 bh = make_uint4(0,0,0,0), bl = make_uint4(0,0,0,0);
            if (n0 + r < N) {
                const size_t boff = (size_t)(n0 + r) * K + k0 + (ch << 3);
                bh = *(const uint4*)(Wh + boff);
                bl = *(const uint4*)(Wl + boff);
            }
            *(uint4*)(sm + stb + 32768 + sw) = bh;
            *(uint4*)(sm + stb + 49152 + sw) = bl;
        }
        asm volatile("fence.proxy.async.shared::cta;" ::: "memory");
        __syncthreads();

        if (warp == 0 && elect1()) {
            const uint64_t ah = mkdesc(sb + stb),         al = mkdesc(sb + stb + 16384);
            const uint64_t bh = mkdesc(sb + stb + 32768), bl = mkdesc(sb + stb + 49152);
#pragma unroll
            for (int kc = 0; kc < 4; kc++) {
                mma_f16_ss(tmem, ah + kc * 2, bh + kc * 2, idesc, (s | kc) != 0);
                mma_f16_ss(tmem, ah + kc * 2, bl + kc * 2, idesc, 1u);
                mma_f16_ss(tmem, al + kc * 2, bh + kc * 2, idesc, 1u);
            }
            asm volatile(
                "tcgen05.commit.cta_group::1.mbarrier::arrive::one.shared::cluster.b64 [%0];"
                :: "r"(st == 0 ? sb + 8 : sb + 16) : "memory");
        }
    }
    // drain outstanding MMA groups
    mbar_wait(sb + 8, ph0);
    if (nsteps > 1) mbar_wait(sb + 16, ph1);
    asm volatile("tcgen05.fence::after_thread_sync;" ::: "memory");

    const int m = m0 + warp * 32 + lane;
#pragma unroll
    for (int base = 0; base < 128; base += 32) {
        uint32_t r[32];
        TC_LD32(r, tmem + base);
        asm volatile("tcgen05.wait::ld.sync.aligned;" ::: "memory");
#pragma unroll
        for (int j = 0; j < 32; j += 4) {
            const int col = n0 + base + j;
            if (col < N) {
                float4 v = make_float4(__uint_as_float(r[j]),   __uint_as_float(r[j+1]),
                                       __uint_as_float(r[j+2]), __uint_as_float(r[j+3]));
                if (EPI == 1) {
                    const float4 b = *(const float4*)(aux + col);
                    v.x = softplusf(v.x + b.x); v.y = softplusf(v.y + b.y);
                    v.z = softplusf(v.z + b.z); v.w = softplusf(v.w + b.w);
                }
                if (EPI == 2) {
                    const float4 a4 = *(const float4*)(aux + (size_t)m * N + col);
                    v.x += a4.x; v.y += a4.y; v.z += a4.z; v.w += a4.w;
                }
                *(float4*)(C + (size_t)m * N + col) = v;
                if (EPI == 3) {
                    uint32_t h0, l0, h1, l1;
                    split2(v.x, v.y, h0, l0);
                    split2(v.z, v.w, h1, l1);
                    *(uint2*)(Ch + (size_t)m * N + col) = make_uint2(h0, h1);
                    *(uint2*)(Cl + (size_t)m * N + col) = make_uint2(l0, l1);
                }
            }
        }
    }

    __syncthreads();
    if (tid == 0) {
        asm volatile("mbarrier.inval.shared.b64 [%0];" :: "r"(sb + 8)  : "memory");
        asm volatile("mbarrier.inval.shared.b64 [%0];" :: "r"(sb + 16) : "memory");
    }
    __syncthreads();
    if (warp == 0)
        asm volatile("tcgen05.dealloc.cta_group::1.sync.aligned.b32 %0, %1;"
                     :: "r"(tmem), "r"(128u));
#else
    // ================= mma.sync fallback (compile-only for non-'a' pass) ============
    __shared__ uint32_t sAh[8][136], sAl[8][136], sBh[8][136], sBl[8][136];
    const int tid  = threadIdx.x;
    const int m0   = blockIdx.y << 7;
    const int n0   = blockIdx.x << 7;
    const int lane = tid & 31, warp = tid >> 5;
    const int wm = (warp >> 1) << 6, wn = (warp & 1) << 6;
    const int g  = lane >> 2,  t  = lane & 3;

    float acc[4][8][4];
#pragma unroll
    for (int i = 0; i < 4; i++)
#pragma unroll
        for (int j = 0; j < 8; j++)
#pragma unroll
            for (int q = 0; q < 4; q++) acc[i][j][q] = 0.f;

#pragma unroll 1
    for (int k0 = 0; k0 < K; k0 += 16) {
#pragma unroll
        for (int i = 0; i < 8; i++) {
            const int idx = tid + (i << 7);
            const int r   = idx >> 3;
            const int k2  = idx & 7;
            sAh[k2][r] = *(const uint32_t*)(Ah + (size_t)(m0 + r) * lda + k0 + k2 * 2);
            sAl[k2][r] = *(const uint32_t*)(Al + (size_t)(m0 + r) * lda + k0 + k2 * 2);
            uint32_t bh = 0, bl = 0;
            if (n0 + r < N) {
                bh = *(const uint32_t*)(Wh + (size_t)(n0 + r) * K + k0 + k2 * 2);
                bl = *(const uint32_t*)(Wl + (size_t)(n0 + r) * K + k0 + k2 * 2);
            }
            sBh[k2][r] = bh; sBl[k2][r] = bl;
        }
        __syncthreads();

        uint32_t bh[8][2], bl[8][2];
#pragma unroll
        for (int nt = 0; nt < 8; nt++) {
            const int nb = wn + (nt << 3) + g;
            bh[nt][0] = sBh[t][nb];     bh[nt][1] = sBh[t+4][nb];
            bl[nt][0] = sBl[t][nb];     bl[nt][1] = sBl[t+4][nb];
        }
#pragma unroll
        for (int mt = 0; mt < 4; mt++) {
            const int mb = wm + (mt << 4) + g;
            uint32_t ah[4] = { sAh[t][mb], sAh[t][mb+8], sAh[t+4][mb], sAh[t+4][mb+8] };
            uint32_t al[4] = { sAl[t][mb], sAl[t][mb+8], sAl[t+4][mb], sAl[t+4][mb+8] };
#pragma unroll
            for (int nt = 0; nt < 8; nt++) {
                mma_bf16(acc[mt][nt], ah, bh[nt]);
                mma_bf16(acc[mt][nt], ah, bl[nt]);
                mma_bf16(acc[mt][nt], al, bh[nt]);
            }
        }
        __syncthreads();
    }

#pragma unroll
    for (int mt = 0; mt < 4; mt++) {
        const int r0 = m0 + wm + (mt << 4) + g;
#pragma unroll
        for (int nt = 0; nt < 8; nt++) {
            const int col = n0 + wn + (nt << 3) + (t << 1);
            if (col < N) {
                float v0 = acc[mt][nt][0], v1 = acc[mt][nt][1];
                float v2 = acc[mt][nt][2], v3 = acc[mt][nt][3];
                if (EPI == 1) {
                    const float b0 = __ldg(&aux[col]), b1 = __ldg(&aux[col+1]);
                    v0 = softplusf(v0 + b0); v1 = softplusf(v1 + b1);
                    v2 = softplusf(v2 + b0); v3 = softplusf(v3 + b1);
                }
                if (EPI == 2) {
                    const float2 a0 = *(const float2*)(aux + (size_t)r0 * N + col);
                    const float2 a1 = *(const float2*)(aux + (size_t)(r0+8) * N + col);
                    v0 += a0.x; v1 += a0.y; v2 += a1.x; v3 += a1.y;
                }
                *(float2*)(C + (size_t)r0     * N + col) = make_float2(v0, v1);
                *(float2*)(C + (size_t)(r0+8) * N + col) = make_float2(v2, v3);
                if (EPI == 3) {
                    uint32_t h, l;
                    split2(v0, v1, h, l);
                    *(uint32_t*)(Ch + (size_t)r0 * N + col) = h;
                    *(uint32_t*)(Cl + (size_t)r0 * N + col) = l;
                    split2(v2, v3, h, l);
                    *(uint32_t*)(Ch + (size_t)(r0+8) * N + col) = h;
                    *(uint32_t*)(Cl + (size_t)(r0+8) * N + col) = l;
                }
            }
        }
    }
#endif
}

// ---------------- depthwise causal/anticausal conv (K=4) + SiLU + split -----------
__global__ void conv_silu_kernel(const float* __restrict__ in, int ldin,
                                 const float* __restrict__ w, const float* __restrict__ bias,
                                 float* __restrict__ outf,
                                 bf16* __restrict__ outh, bf16* __restrict__ outl,
                                 int backward)
{
    const int idx = blockIdx.x * 256 + threadIdx.x;
    const int dd  = idx & (DI - 1);
    const int tok = idx >> 10;
    const int l   = tok & (LL - 1);
    const float* base = in + (size_t)(tok - l) * ldin + dd;
    const float w0 = w[dd*4+0], w1 = w[dd*4+1], w2 = w[dd*4+2], w3 = w[dd*4+3];
    float acc = bias[dd];
    if (!backward) {
        if (l >= 3) acc += base[(size_t)(l-3)*ldin] * w0;
        if (l >= 2) acc += base[(size_t)(l-2)*ldin] * w1;
        if (l >= 1) acc += base[(size_t)(l-1)*ldin] * w2;
        acc += base[(size_t)l*ldin] * w3;
    } else {
        acc += base[(size_t)l*ldin] * w3;
        if (l+1 < LL) acc += base[(size_t)(l+1)*ldin] * w2;
        if (l+2 < LL) acc += base[(size_t)(l+2)*ldin] * w1;
        if (l+3 < LL) acc += base[(size_t)(l+3)*ldin] * w0;
    }
    const float v = siluf(acc);
    if (outf) outf[idx] = v;
    const bf16 h = __float2bfloat16(v);
    outh[idx] = h;
    outl[idx] = __float2bfloat16(v - __bfloat162float(h));
}

// ---------------- selective scan + fused gating -> split bf16 ----------------
__global__ __launch_bounds__(256) void scan_kernel(
    const float* __restrict__ u, const float* __restrict__ dt,
    const float* __restrict__ xdbl, const float* __restrict__ xz,
    const float* __restrict__ Alog, const float* __restrict__ Dp,
    bf16* __restrict__ ygh, bf16* __restrict__ ygl, int backward)
{
    __shared__ float s_u[64][16], s_dt[64][16], s_B[64][16], s_C[64][16], s_y[64][16];
    const int b     = blockIdx.x >> 6;
    const int dbase = (blockIdx.x & 63) << 4;
    const int tid = threadIdx.x;
    const int dl  = tid >> 4;
    const int n   = tid & 15;
    const int d   = dbase + dl;
    const float a    = -expf(Alog[d * DST + n]);
    const float Dloc = Dp[d];
    float h = 0.f;
    const size_t brow = (size_t)b * LL;

    for (int chunk = 0; chunk < LL / 64; chunk++) {
        const int c0 = chunk << 6;
#pragma unroll
        for (int i = 0; i < 4; i++) {
            const int ii = tid + (i << 8);
            const int tt = ii >> 4, dc = ii & 15;
            const int t = c0 + tt;
            const int l = backward ? (LL - 1 - t) : t;
            const size_t roff = brow + l;
            s_u [tt][dc] = u [roff * DI + dbase + dc];
            s_dt[tt][dc] = dt[roff * DI + dbase + dc];
            s_B [tt][dc] = xdbl[roff * XD + 64 + dc];
            s_C [tt][dc] = xdbl[roff * XD + 80 + dc];
        }
        __syncthreads();
#pragma unroll 8
        for (int tt = 0; tt < 64; tt++) {
            const float dtv = s_dt[tt][dl];
            const float uv  = s_u [tt][dl];
            const float dA  = __expf(dtv * a);
            const float db  = dtv * uv * s_B[tt][n];
            h = fmaf(dA, h, db);
            float yp = h * s_C[tt][n];
            yp += __shfl_xor_sync(0xffffffffu, yp, 8);
            yp += __shfl_xor_sync(0xffffffffu, yp, 4);
            yp += __shfl_xor_sync(0xffffffffu, yp, 2);
            yp += __shfl_xor_sync(0xffffffffu, yp, 1);
            if (n == 0) s_y[tt][dl] = fmaf(uv, Dloc, yp);
        }
        __syncthreads();
#pragma unroll
        for (int i = 0; i < 4; i++) {
            const int ii = tid + (i << 8);
            const int tt = ii >> 4, dc = ii & 15;
            const int t = c0 + tt;
            const int l = backward ? (LL - 1 - t) : t;
            const size_t roff = brow + l;
            const float z = xz[roff * DI2 + DI + dbase + dc];
            const float v = s_y[tt][dc] * siluf(z);
            const bf16 hv = __float2bfloat16(v);
            ygh[roff * DI + dbase + dc] = hv;
            ygl[roff * DI + dbase + dc] = __float2bfloat16(v - __bfloat162float(hv));
        }
        __syncthreads();
    }
}

// ---------------- final gate/concat -> split bf16 ----------------
__global__ void ymix_kernel(const float* __restrict__ mo0, const float* __restrict__ mo1,
                            const float* __restrict__ xp,
                            bf16* __restrict__ ymh, bf16* __restrict__ yml)
{
    const int idx = blockIdx.x * 256 + threadIdx.x;
    const int dd  = idx & (DI - 1);
    const int tok = idx >> 10;
    const float g = siluf(xp[(size_t)tok * DI2 + DI + dd]);
    const float v0 = mo0[idx] * g;
    const float v1 = mo1[idx] * g;
    const bf16 h0 = __float2bfloat16(v0);
    const bf16 h1 = __float2bfloat16(v1);
    ymh[(size_t)tok * DI2 + dd]      = h0;
    yml[(size_t)tok * DI2 + dd]      = __float2bfloat16(v0 - __bfloat162float(h0));
    ymh[(size_t)tok * DI2 + DI + dd] = h1;
    yml[(size_t)tok * DI2 + DI + dd] = __float2bfloat16(v1 - __bfloat162float(h1));
}

// ---------------- host ----------------
extern "C" void kernel_launch(void* const* d_in, const int* in_sizes, int n_in,
                              void* d_out, int out_size)
{
    const float* x      = (const float*)d_in[0];
    const float* norm_g = (const float*)d_in[1];
    const float* norm_b = (const float*)d_in[2];
    const float* in_w   = (const float*)d_in[3];
    const float* conv_w = (const float*)d_in[4];
    const float* conv_b = (const float*)d_in[5];
    const float* out_w  = (const float*)d_in[6];
    const float* P[2][9];
    for (int p = 0; p < 2; p++)
        for (int i = 0; i < 9; i++)
            P[p][i] = (const float*)d_in[7 + p * 9 + i];
    // P[p]: 0 in_w, 1 conv_w, 2 conv_b, 3 xp_w, 4 dt_w, 5 dt_b, 6 Alog, 7 D, 8 out_w

    cudaFuncSetAttribute(gemm5<0>, cudaFuncAttributeMaxDynamicSharedMemorySize, SM_TOT);
    cudaFuncSetAttribute(gemm5<1>, cudaFuncAttributeMaxDynamicSharedMemorySize, SM_TOT);
    cudaFuncSetAttribute(gemm5<2>, cudaFuncAttributeMaxDynamicSharedMemorySize, SM_TOT);
    cudaFuncSetAttribute(gemm5<3>, cudaFuncAttributeMaxDynamicSharedMemorySize, SM_TOT);

    float *xp, *xz, *xma, *xdbl, *dtb, *mo;
    bf16 *xnh, *xnl, *xah, *xal, *xmh, *xml, *xdh, *xdl, *ygh, *ygl, *ymh, *yml, *wh, *wl;
    cudaGetSymbolAddress((void**)&xp,   g_xp);
    cudaGetSymbolAddress((void**)&xz,   g_xz);
    cudaGetSymbolAddress((void**)&xma,  g_xma);
    cudaGetSymbolAddress((void**)&xdbl, g_xdbl);
    cudaGetSymbolAddress((void**)&dtb,  g_dt);
    cudaGetSymbolAddress((void**)&mo,   g_mo);
    cudaGetSymbolAddress((void**)&xnh,  g_xnh);  cudaGetSymbolAddress((void**)&xnl, g_xnl);
    cudaGetSymbolAddress((void**)&xah,  g_xah);  cudaGetSymbolAddress((void**)&xal, g_xal);
    cudaGetSymbolAddress((void**)&xmh,  g_xmh);  cudaGetSymbolAddress((void**)&xml, g_xml);
    cudaGetSymbolAddress((void**)&xdh,  g_xdh);  cudaGetSymbolAddress((void**)&xdl, g_xdl);
    cudaGetSymbolAddress((void**)&ygh,  g_ygh);  cudaGetSymbolAddress((void**)&ygl, g_ygl);
    cudaGetSymbolAddress((void**)&ymh,  g_ymh);  cudaGetSymbolAddress((void**)&yml, g_yml);
    cudaGetSymbolAddress((void**)&wh,   g_wh);   cudaGetSymbolAddress((void**)&wl,  g_wl);

    const int EW_GRID = NTOK * DI / 256;
    const int MB = NTOK / 128;   // 64 M-blocks

    // LN -> split xn
    ln_kernel<<<NTOK, 128>>>(x, norm_g, norm_b, xnh, xnl);

    // xp = xn @ in_w^T
    split_kernel<<<DI2 * DMODEL / 4 / 256, 256>>>(in_w, wh, wl, DI2 * DMODEL / 4);
    gemm5<0><<<dim3(DI2 / 128, MB), 128, SM_TOT>>>(xnh, xnl, DMODEL, wh, wl,
                                                   xp, DI2, DMODEL, nullptr, nullptr, nullptr);

    // xa = silu(causal dwconv(xp[:, :DI])) -> split only
    conv_silu_kernel<<<EW_GRID, 256>>>(xp, DI2, conv_w, conv_b, nullptr, xah, xal, 0);

    for (int p = 0; p < 2; p++) {
        float* mop = mo + (size_t)p * NTOK * DI;

        // xz = xa @ p_in_w^T
        split_kernel<<<DI2 * DI / 4 / 256, 256>>>(P[p][0], wh, wl, DI2 * DI / 4);
        gemm5<0><<<dim3(DI2 / 128, MB), 128, SM_TOT>>>(xah, xal, DI, wh, wl,
                                                       xz, DI2, DI, nullptr, nullptr, nullptr);
        // xm = silu(dwconv(xz[:, :DI])) -> fp32 (scan u) + split (xdbl GEMM)
        conv_silu_kernel<<<EW_GRID, 256>>>(xz, DI2, P[p][1], P[p][2], xma, xmh, xml, p);
        // xdbl = xm @ xp_w^T -> fp32 + split
        split_kernel<<<XD * DI / 4 / 256, 256>>>(P[p][3], wh, wl, XD * DI / 4);
        gemm5<3><<<dim3(1, MB), 128, SM_TOT>>>(xmh, xml, DI, wh, wl,
                                               xdbl, XD, DI, nullptr, xdh, xdl);
        // dt = softplus(xdbl[:, :64] @ dt_w^T + dt_b)
        split_kernel<<<DI * DTR / 4 / 256, 256>>>(P[p][4], wh, wl, DI * DTR / 4);
        gemm5<1><<<dim3(DI / 128, MB), 128, SM_TOT>>>(xdh, xdl, XD, wh, wl,
                                                      dtb, DI, DTR, P[p][5], nullptr, nullptr);
        // scan + fused y*silu(z) -> split yg
        scan_kernel<<<BN_ * (DI / 16), 256>>>(xma, dtb, xdbl, xz, P[p][6], P[p][7],
                                              ygh, ygl, p);
        // mamba out = yg @ out_w^T -> fp32 mo[p]
        split_kernel<<<DI * DI / 4 / 256, 256>>>(P[p][8], wh, wl, DI * DI / 4);
        gemm5<0><<<dim3(DI / 128, MB), 128, SM_TOT>>>(ygh, ygl, DI, wh, wl,
                                                      mop, DI, DI, nullptr, nullptr, nullptr);
    }

    // ym = [yf*g, yb*g] -> split
    ymix_kernel<<<EW_GRID, 256>>>(mo, mo + (size_t)NTOK * DI, xp, ymh, yml);

    // out = ym @ out_w^T + x
    split_kernel<<<DMODEL * DI2 / 4 / 256, 256>>>(out_w, wh, wl, DMODEL * DI2 / 4);
    gemm5<2><<<dim3(DMODEL / 128, MB), 128, SM_TOT>>>(ymh, yml, DI2, wh, wl,
                                                      (float*)d_out, DMODEL, DI2, x,
                                                      nullptr, nullptr);
}

// round 10
// speedup vs baseline: 2.2422x; 2.2422x over previous
#include <cuda_runtime.h>
#include <cuda_bf16.h>
#include <math.h>
#include <stdint.h>

#define BN_    4
#define LL     2048
#define DMODEL 512
#define DI     1024
#define DI2    2048
#define DST    16
#define DTR    64
#define XD     96
#define NTOK   8192   // B * L

// tcgen05 only exists on the arch-specific target (sm_103a / sm_100a).
#if defined(__CUDA_ARCH_FEAT_SM103_ALL) || defined(__CUDA_ARCH_FEAT_SM100_ALL)
#define HAS_TC5 1
#endif

typedef __nv_bfloat16 bf16;

// ---------------- scratch (device globals: no allocation allowed) ----------------
__device__ float g_xp  [(size_t)NTOK * DI2];
__device__ float g_xz  [(size_t)NTOK * DI2];
__device__ float g_xma [(size_t)NTOK * DI];
__device__ float g_xdbl[(size_t)NTOK * XD];
__device__ float g_dt  [(size_t)NTOK * DI];
__device__ float g_mo  [2][(size_t)NTOK * DI];
// bf16 hi/lo pre-split GEMM operands
__device__ bf16 g_xnh[(size_t)NTOK * DMODEL], g_xnl[(size_t)NTOK * DMODEL];
__device__ bf16 g_xah[(size_t)NTOK * DI],     g_xal[(size_t)NTOK * DI];
__device__ bf16 g_xmh[(size_t)NTOK * DI],     g_xml[(size_t)NTOK * DI];
__device__ bf16 g_xdh[(size_t)NTOK * XD],     g_xdl[(size_t)NTOK * XD];
__device__ bf16 g_ygh[(size_t)NTOK * DI],     g_ygl[(size_t)NTOK * DI];
__device__ bf16 g_ymh[(size_t)NTOK * DI2],    g_yml[(size_t)NTOK * DI2];
// weight split scratch (reused sequentially; max weight = 2M elems)
__device__ bf16 g_wh[(size_t)2 * 1024 * 1024], g_wl[(size_t)2 * 1024 * 1024];

__device__ __forceinline__ float siluf(float x)     { return x / (1.f + __expf(-x)); }
__device__ __forceinline__ float softplusf(float x) { return x > 20.f ? x : log1pf(__expf(x)); }

__device__ __forceinline__ uint32_t pack_bf16x2(float x, float y) {
    uint32_t r;
    asm("cvt.rn.bf16x2.f32 %0, %1, %2;" : "=r"(r) : "f"(y), "f"(x));  // {lo=x, hi=y}
    return r;
}
__device__ __forceinline__ void split2(float x, float y, uint32_t& h, uint32_t& l) {
    h = pack_bf16x2(x, y);
    const float rx = __uint_as_float(h << 16);
    const float ry = __uint_as_float(h & 0xffff0000u);
    l = pack_bf16x2(x - rx, y - ry);
}

// ---------------- weight split: fp32[n] -> hi/lo bf16 ----------------
__global__ void split_kernel(const float* __restrict__ in, bf16* __restrict__ hi,
                             bf16* __restrict__ lo, int n4)
{
    const int i = blockIdx.x * 256 + threadIdx.x;
    if (i < n4) {
        const float4 v = ((const float4*)in)[i];
        uint32_t h0, l0, h1, l1;
        split2(v.x, v.y, h0, l0);
        split2(v.z, v.w, h1, l1);
        ((uint2*)hi)[i] = make_uint2(h0, h1);
        ((uint2*)lo)[i] = make_uint2(l0, l1);
    }
}

// ---------------- LayerNorm -> split bf16 ----------------
__global__ void ln_kernel(const float* __restrict__ x, const float* __restrict__ gg,
                          const float* __restrict__ bb,
                          bf16* __restrict__ hi, bf16* __restrict__ lo)
{
    __shared__ float red[8];
    const int row = blockIdx.x;
    const int t   = threadIdx.x;
    float4 v = ((const float4*)(x + (size_t)row * DMODEL))[t];
    float s = v.x + v.y + v.z + v.w;
#pragma unroll
    for (int o = 16; o; o >>= 1) s += __shfl_xor_sync(0xffffffffu, s, o);
    if ((t & 31) == 0) red[t >> 5] = s;
    __syncthreads();
    const float mu = (red[0] + red[1] + red[2] + red[3]) * (1.f / DMODEL);
    const float dx = v.x - mu, dy = v.y - mu, dz = v.z - mu, dw = v.w - mu;
    float vs = dx*dx + dy*dy + dz*dz + dw*dw;
#pragma unroll
    for (int o = 16; o; o >>= 1) vs += __shfl_xor_sync(0xffffffffu, vs, o);
    if ((t & 31) == 0) red[4 + (t >> 5)] = vs;
    __syncthreads();
    const float var = (red[4] + red[5] + red[6] + red[7]) * (1.f / DMODEL);
    const float inv = rsqrtf(var + 1e-5f);
    const int i0 = t << 2;
    float ox = dx * inv * gg[i0+0] + bb[i0+0];
    float oy = dy * inv * gg[i0+1] + bb[i0+1];
    float oz = dz * inv * gg[i0+2] + bb[i0+2];
    float ow = dw * inv * gg[i0+3] + bb[i0+3];
    uint32_t h0, l0, h1, l1;
    split2(ox, oy, h0, l0);
    split2(oz, ow, h1, l1);
    ((uint2*)(hi + (size_t)row * DMODEL))[t] = make_uint2(h0, h1);
    ((uint2*)(lo + (size_t)row * DMODEL))[t] = make_uint2(l0, l1);
}

#ifdef HAS_TC5
// ---------------- tcgen05 helpers ----------------
__device__ __forceinline__ uint32_t smem_u32(const void* p) {
    uint32_t a;
    asm("{ .reg .u64 t; cvta.to.shared.u64 t, %1; cvt.u32.u64 %0, t; }" : "=r"(a) : "l"(p));
    return a;
}
__device__ __forceinline__ uint32_t elect1() {
    uint32_t p;
    asm volatile("{\n\t.reg .pred p;\n\telect.sync _|p, 0xFFFFFFFF;\n\tselp.b32 %0, 1, 0, p;\n\t}"
                 : "=r"(p));
    return p;
}
__device__ __forceinline__ uint32_t swz(uint32_t off) { return off ^ ((off >> 3) & 0x70); }

// SW128 K-major smem descriptor (Blackwell): layout=2, version=1, SBO=64, LBO=1
static __device__ __forceinline__ uint64_t mkdesc(uint32_t addr) {
    const uint64_t base = (2ull << 61) | (1ull << 46) | (64ull << 32) | (1ull << 16);
    return base | ((addr >> 4) & 0x3FFFu);
}

__device__ __forceinline__ void mma_f16_ss(uint32_t d, uint64_t a, uint64_t b,
                                           uint32_t idesc, uint32_t en) {
    asm volatile(
        "{\n\t.reg .pred p;\n\tsetp.ne.u32 p, %4, 0;\n\t"
        "tcgen05.mma.cta_group::1.kind::f16 [%0], %1, %2, %3, {%5,%5,%5,%5}, p;\n\t}"
        :: "r"(d), "l"(a), "l"(b), "r"(idesc), "r"(en), "r"(0u) : "memory");
}

__device__ __forceinline__ void mbar_wait(uint32_t mbar, uint32_t parity) {
    asm volatile(
        "{\n\t.reg .pred P;\n\t"
        "W_%=:\n\t"
        "mbarrier.try_wait.parity.acquire.cta.shared::cta.b64 P, [%0], %1, 0x989680;\n\t"
        "@P bra.uni D_%=;\n\t"
        "bra.uni W_%=;\n\t"
        "D_%=:\n\t}"
        :: "r"(mbar), "r"(parity) : "memory");
}

#define TC_LD32(r, addr) \
    asm volatile( \
        "tcgen05.ld.sync.aligned.32x32b.x32.b32 " \
        "{%0, %1, %2, %3, %4, %5, %6, %7, " \
        " %8, %9, %10, %11, %12, %13, %14, %15, " \
        " %16, %17, %18, %19, %20, %21, %22, %23, " \
        " %24, %25, %26, %27, %28, %29, %30, %31}, [%32];" \
        : "=r"((r)[0]),  "=r"((r)[1]),  "=r"((r)[2]),  "=r"((r)[3]), \
          "=r"((r)[4]),  "=r"((r)[5]),  "=r"((r)[6]),  "=r"((r)[7]), \
          "=r"((r)[8]),  "=r"((r)[9]),  "=r"((r)[10]), "=r"((r)[11]), \
          "=r"((r)[12]), "=r"((r)[13]), "=r"((r)[14]), "=r"((r)[15]), \
          "=r"((r)[16]), "=r"((r)[17]), "=r"((r)[18]), "=r"((r)[19]), \
          "=r"((r)[20]), "=r"((r)[21]), "=r"((r)[22]), "=r"((r)[23]), \
          "=r"((r)[24]), "=r"((r)[25]), "=r"((r)[26]), "=r"((r)[27]), \
          "=r"((r)[28]), "=r"((r)[29]), "=r"((r)[30]), "=r"((r)[31]) \
        : "r"(addr))
#else
__device__ __forceinline__ void mma_bf16(float* c, const uint32_t* a, const uint32_t* b) {
    asm volatile("mma.sync.aligned.m16n8k16.row.col.f32.bf16.bf16.f32 "
        "{%0,%1,%2,%3}, {%4,%5,%6,%7}, {%8,%9}, {%0,%1,%2,%3};"
        : "+f"(c[0]), "+f"(c[1]), "+f"(c[2]), "+f"(c[3])
        : "r"(a[0]), "r"(a[1]), "r"(a[2]), "r"(a[3]), "r"(b[0]), "r"(b[1]));
}
#endif

// ---------------- GEMM: C[M,N] = (Ah+Al)[M,K] @ (Wh+Wl)[N,K]^T, 3-pass split -------
// Pre-split bf16 inputs. Single-stage 64KB smem -> 3 CTAs/SM (cross-CTA pipelining).
// M mult of 128, K mult of 64, N mult of 4 (tile zero-padded to 128).
// EPI: 0 none, 1 softplus(acc+aux[n]), 2 acc+aux[m*N+n], 3 fp32 C + split (Ch,Cl).
#define SM_TOT (1024 + 65536)   // hdr + 4 tiles x 16KB

template<int EPI>
__global__ void __launch_bounds__(128)
gemm5(const bf16* __restrict__ Ah, const bf16* __restrict__ Al, int lda,
      const bf16* __restrict__ Wh, const bf16* __restrict__ Wl,
      float* __restrict__ C, int N, int K, const float* __restrict__ aux,
      bf16* __restrict__ Ch, bf16* __restrict__ Cl)
{
#ifdef HAS_TC5
    // ================= tcgen05 path (sm_103a SASS) =================
    extern __shared__ __align__(1024) char sm[];
    const uint32_t sb = smem_u32(sm);
    const int tid = threadIdx.x, warp = tid >> 5, lane = tid & 31;
    const int m0 = blockIdx.y << 7, n0 = blockIdx.x << 7;

    if (warp == 0) {
        asm volatile("tcgen05.alloc.cta_group::1.sync.aligned.shared::cta.b32 [%0], %1;"
                     :: "r"(sb), "r"(128u) : "memory");
        asm volatile("tcgen05.relinquish_alloc_permit.cta_group::1.sync.aligned;");
    }
    if (tid == 0)
        asm volatile("mbarrier.init.shared.b64 [%0], %1;" :: "r"(sb + 8), "r"(1u) : "memory");
    __syncthreads();
    uint32_t tmem;
    asm volatile("ld.shared.b32 %0, [%1];" : "=r"(tmem) : "r"(sb));

    const uint32_t idesc = 0x8200490u;   // M=128, N=128, bf16 x bf16 -> f32
    uint32_t phase = 0;

    for (int k0 = 0; k0 < K; k0 += 64) {
        // fill: pure bf16 copies into SW128-swizzled tiles
#pragma unroll
        for (int i = 0; i < 8; i++) {
            const int idx = tid + (i << 7);          // 0..1023
            const int r   = idx >> 3;                // row 0..127
            const int ch  = idx & 7;                 // 16B chunk (8 bf16)
            const uint32_t sw = swz((uint32_t)(r * 128 + ch * 16));
            const size_t aoff = (size_t)(m0 + r) * lda + k0 + (ch << 3);
            *(uint4*)(sm + 1024 + 0     + sw) = *(const uint4*)(Ah + aoff);
            *(uint4*)(sm + 1024 + 16384 + sw) = *(const uint4*)(Al + aoff);
            uint4 bh = make_uint4(0,0,0,0), bl = make_uint4(0,0,0,0);
            if (n0 + r < N) {
                const size_t boff = (size_t)(n0 + r) * K + k0 + (ch << 3);
                bh = *(const uint4*)(Wh + boff);
                bl = *(const uint4*)(Wl + boff);
            }
            *(uint4*)(sm + 1024 + 32768 + sw) = bh;
            *(uint4*)(sm + 1024 + 49152 + sw) = bl;
        }
        asm volatile("fence.proxy.async.shared::cta;" ::: "memory");
        __syncthreads();

        if (warp == 0 && elect1()) {
            const uint64_t ah = mkdesc(sb + 1024),         al = mkdesc(sb + 1024 + 16384);
            const uint64_t bh = mkdesc(sb + 1024 + 32768), bl = mkdesc(sb + 1024 + 49152);
#pragma unroll
            for (int kc = 0; kc < 4; kc++) {
                mma_f16_ss(tmem, ah + kc * 2, bh + kc * 2, idesc, (k0 | kc) != 0);
                mma_f16_ss(tmem, ah + kc * 2, bl + kc * 2, idesc, 1u);
                mma_f16_ss(tmem, al + kc * 2, bh + kc * 2, idesc, 1u);
            }
            asm volatile(
                "tcgen05.commit.cta_group::1.mbarrier::arrive::one.shared::cluster.b64 [%0];"
                :: "r"(sb + 8) : "memory");
        }
        mbar_wait(sb + 8, phase);
        phase ^= 1;
    }

    asm volatile("tcgen05.fence::after_thread_sync;" ::: "memory");

    const int m = m0 + warp * 32 + lane;
#pragma unroll
    for (int base = 0; base < 128; base += 32) {
        uint32_t r[32];
        TC_LD32(r, tmem + base);
        asm volatile("tcgen05.wait::ld.sync.aligned;" ::: "memory");
#pragma unroll
        for (int j = 0; j < 32; j += 4) {
            const int col = n0 + base + j;
            if (col < N) {
                float4 v = make_float4(__uint_as_float(r[j]),   __uint_as_float(r[j+1]),
                                       __uint_as_float(r[j+2]), __uint_as_float(r[j+3]));
                if (EPI == 1) {
                    const float4 b = *(const float4*)(aux + col);
                    v.x = softplusf(v.x + b.x); v.y = softplusf(v.y + b.y);
                    v.z = softplusf(v.z + b.z); v.w = softplusf(v.w + b.w);
                }
                if (EPI == 2) {
                    const float4 a4 = *(const float4*)(aux + (size_t)m * N + col);
                    v.x += a4.x; v.y += a4.y; v.z += a4.z; v.w += a4.w;
                }
                *(float4*)(C + (size_t)m * N + col) = v;
                if (EPI == 3) {
                    uint32_t h0, l0, h1, l1;
                    split2(v.x, v.y, h0, l0);
                    split2(v.z, v.w, h1, l1);
                    *(uint2*)(Ch + (size_t)m * N + col) = make_uint2(h0, h1);
                    *(uint2*)(Cl + (size_t)m * N + col) = make_uint2(l0, l1);
                }
            }
        }
    }

    __syncthreads();
    if (tid == 0)
        asm volatile("mbarrier.inval.shared.b64 [%0];" :: "r"(sb + 8) : "memory");
    __syncthreads();
    if (warp == 0)
        asm volatile("tcgen05.dealloc.cta_group::1.sync.aligned.b32 %0, %1;"
                     :: "r"(tmem), "r"(128u));
#else
    // ================= mma.sync fallback (compile-only for non-'a' pass) ============
    __shared__ uint32_t sAh[8][136], sAl[8][136], sBh[8][136], sBl[8][136];
    const int tid  = threadIdx.x;
    const int m0   = blockIdx.y << 7;
    const int n0   = blockIdx.x << 7;
    const int lane = tid & 31, warp = tid >> 5;
    const int wm = (warp >> 1) << 6, wn = (warp & 1) << 6;
    const int g  = lane >> 2,  t  = lane & 3;

    float acc[4][8][4];
#pragma unroll
    for (int i = 0; i < 4; i++)
#pragma unroll
        for (int j = 0; j < 8; j++)
#pragma unroll
            for (int q = 0; q < 4; q++) acc[i][j][q] = 0.f;

#pragma unroll 1
    for (int k0 = 0; k0 < K; k0 += 16) {
#pragma unroll
        for (int i = 0; i < 8; i++) {
            const int idx = tid + (i << 7);
            const int r   = idx >> 3;
            const int k2  = idx & 7;
            sAh[k2][r] = *(const uint32_t*)(Ah + (size_t)(m0 + r) * lda + k0 + k2 * 2);
            sAl[k2][r] = *(const uint32_t*)(Al + (size_t)(m0 + r) * lda + k0 + k2 * 2);
            uint32_t bh = 0, bl = 0;
            if (n0 + r < N) {
                bh = *(const uint32_t*)(Wh + (size_t)(n0 + r) * K + k0 + k2 * 2);
                bl = *(const uint32_t*)(Wl + (size_t)(n0 + r) * K + k0 + k2 * 2);
            }
            sBh[k2][r] = bh; sBl[k2][r] = bl;
        }
        __syncthreads();

        uint32_t bh[8][2], bl[8][2];
#pragma unroll
        for (int nt = 0; nt < 8; nt++) {
            const int nb = wn + (nt << 3) + g;
            bh[nt][0] = sBh[t][nb];     bh[nt][1] = sBh[t+4][nb];
            bl[nt][0] = sBl[t][nb];     bl[nt][1] = sBl[t+4][nb];
        }
#pragma unroll
        for (int mt = 0; mt < 4; mt++) {
            const int mb = wm + (mt << 4) + g;
            uint32_t ah[4] = { sAh[t][mb], sAh[t][mb+8], sAh[t+4][mb], sAh[t+4][mb+8] };
            uint32_t al[4] = { sAl[t][mb], sAl[t][mb+8], sAl[t+4][mb], sAl[t+4][mb+8] };
#pragma unroll
            for (int nt = 0; nt < 8; nt++) {
                mma_bf16(acc[mt][nt], ah, bh[nt]);
                mma_bf16(acc[mt][nt], ah, bl[nt]);
                mma_bf16(acc[mt][nt], al, bh[nt]);
            }
        }
        __syncthreads();
    }

#pragma unroll
    for (int mt = 0; mt < 4; mt++) {
        const int r0 = m0 + wm + (mt << 4) + g;
#pragma unroll
        for (int nt = 0; nt < 8; nt++) {
            const int col = n0 + wn + (nt << 3) + (t << 1);
            if (col < N) {
                float v0 = acc[mt][nt][0], v1 = acc[mt][nt][1];
                float v2 = acc[mt][nt][2], v3 = acc[mt][nt][3];
                if (EPI == 1) {
                    const float b0 = __ldg(&aux[col]), b1 = __ldg(&aux[col+1]);
                    v0 = softplusf(v0 + b0); v1 = softplusf(v1 + b1);
                    v2 = softplusf(v2 + b0); v3 = softplusf(v3 + b1);
                }
                if (EPI == 2) {
                    const float2 a0 = *(const float2*)(aux + (size_t)r0 * N + col);
                    const float2 a1 = *(const float2*)(aux + (size_t)(r0+8) * N + col);
                    v0 += a0.x; v1 += a0.y; v2 += a1.x; v3 += a1.y;
                }
                *(float2*)(C + (size_t)r0     * N + col) = make_float2(v0, v1);
                *(float2*)(C + (size_t)(r0+8) * N + col) = make_float2(v2, v3);
                if (EPI == 3) {
                    uint32_t h, l;
                    split2(v0, v1, h, l);
                    *(uint32_t*)(Ch + (size_t)r0 * N + col) = h;
                    *(uint32_t*)(Cl + (size_t)r0 * N + col) = l;
                    split2(v2, v3, h, l);
                    *(uint32_t*)(Ch + (size_t)(r0+8) * N + col) = h;
                    *(uint32_t*)(Cl + (size_t)(r0+8) * N + col) = l;
                }
            }
        }
    }
#endif
}

// ---------------- depthwise causal/anticausal conv (K=4) + SiLU + split -----------
__global__ void conv_silu_kernel(const float* __restrict__ in, int ldin,
                                 const float* __restrict__ w, const float* __restrict__ bias,
                                 float* __restrict__ outf,
                                 bf16* __restrict__ outh, bf16* __restrict__ outl,
                                 int backward)
{
    const int idx = blockIdx.x * 256 + threadIdx.x;
    const int dd  = idx & (DI - 1);
    const int tok = idx >> 10;
    const int l   = tok & (LL - 1);
    const float* base = in + (size_t)(tok - l) * ldin + dd;
    const float w0 = w[dd*4+0], w1 = w[dd*4+1], w2 = w[dd*4+2], w3 = w[dd*4+3];
    float acc = bias[dd];
    if (!backward) {
        if (l >= 3) acc += base[(size_t)(l-3)*ldin] * w0;
        if (l >= 2) acc += base[(size_t)(l-2)*ldin] * w1;
        if (l >= 1) acc += base[(size_t)(l-1)*ldin] * w2;
        acc += base[(size_t)l*ldin] * w3;
    } else {
        acc += base[(size_t)l*ldin] * w3;
        if (l+1 < LL) acc += base[(size_t)(l+1)*ldin] * w2;
        if (l+2 < LL) acc += base[(size_t)(l+2)*ldin] * w1;
        if (l+3 < LL) acc += base[(size_t)(l+3)*ldin] * w0;
    }
    const float v = siluf(acc);
    if (outf) outf[idx] = v;
    const bf16 h = __float2bfloat16(v);
    outh[idx] = h;
    outl[idx] = __float2bfloat16(v - __bfloat162float(h));
}

// ---------------- selective scan + fused gating -> split bf16 ----------------
__global__ __launch_bounds__(256) void scan_kernel(
    const float* __restrict__ u, const float* __restrict__ dt,
    const float* __restrict__ xdbl, const float* __restrict__ xz,
    const float* __restrict__ Alog, const float* __restrict__ Dp,
    bf16* __restrict__ ygh, bf16* __restrict__ ygl, int backward)
{
    __shared__ float s_u[64][16], s_dt[64][16], s_B[64][16], s_C[64][16], s_y[64][16];
    const int b     = blockIdx.x >> 6;
    const int dbase = (blockIdx.x & 63) << 4;
    const int tid = threadIdx.x;
    const int dl  = tid >> 4;
    const int n   = tid & 15;
    const int d   = dbase + dl;
    const float a    = -expf(Alog[d * DST + n]);
    const float Dloc = Dp[d];
    float h = 0.f;
    const size_t brow = (size_t)b * LL;

    for (int chunk = 0; chunk < LL / 64; chunk++) {
        const int c0 = chunk << 6;
#pragma unroll
        for (int i = 0; i < 4; i++) {
            const int ii = tid + (i << 8);
            const int tt = ii >> 4, dc = ii & 15;
            const int t = c0 + tt;
            const int l = backward ? (LL - 1 - t) : t;
            const size_t roff = brow + l;
            s_u [tt][dc] = u [roff * DI + dbase + dc];
            s_dt[tt][dc] = dt[roff * DI + dbase + dc];
            s_B [tt][dc] = xdbl[roff * XD + 64 + dc];
            s_C [tt][dc] = xdbl[roff * XD + 80 + dc];
        }
        __syncthreads();
#pragma unroll 8
        for (int tt = 0; tt < 64; tt++) {
            const float dtv = s_dt[tt][dl];
            const float uv  = s_u [tt][dl];
            const float dA  = __expf(dtv * a);
            const float db  = dtv * uv * s_B[tt][n];
            h = fmaf(dA, h, db);
            float yp = h * s_C[tt][n];
            yp += __shfl_xor_sync(0xffffffffu, yp, 8);
            yp += __shfl_xor_sync(0xffffffffu, yp, 4);
            yp += __shfl_xor_sync(0xffffffffu, yp, 2);
            yp += __shfl_xor_sync(0xffffffffu, yp, 1);
            if (n == 0) s_y[tt][dl] = fmaf(uv, Dloc, yp);
        }
        __syncthreads();
#pragma unroll
        for (int i = 0; i < 4; i++) {
            const int ii = tid + (i << 8);
            const int tt = ii >> 4, dc = ii & 15;
            const int t = c0 + tt;
            const int l = backward ? (LL - 1 - t) : t;
            const size_t roff = brow + l;
            const float z = xz[roff * DI2 + DI + dbase + dc];
            const float v = s_y[tt][dc] * siluf(z);
            const bf16 hv = __float2bfloat16(v);
            ygh[roff * DI + dbase + dc] = hv;
            ygl[roff * DI + dbase + dc] = __float2bfloat16(v - __bfloat162float(hv));
        }
        __syncthreads();
    }
}

// ---------------- final gate/concat -> split bf16 ----------------
__global__ void ymix_kernel(const float* __restrict__ mo0, const float* __restrict__ mo1,
                            const float* __restrict__ xp,
                            bf16* __restrict__ ymh, bf16* __restrict__ yml)
{
    const int idx = blockIdx.x * 256 + threadIdx.x;
    const int dd  = idx & (DI - 1);
    const int tok = idx >> 10;
    const float g = siluf(xp[(size_t)tok * DI2 + DI + dd]);
    const float v0 = mo0[idx] * g;
    const float v1 = mo1[idx] * g;
    const bf16 h0 = __float2bfloat16(v0);
    const bf16 h1 = __float2bfloat16(v1);
    ymh[(size_t)tok * DI2 + dd]      = h0;
    yml[(size_t)tok * DI2 + dd]      = __float2bfloat16(v0 - __bfloat162float(h0));
    ymh[(size_t)tok * DI2 + DI + dd] = h1;
    yml[(size_t)tok * DI2 + DI + dd] = __float2bfloat16(v1 - __bfloat162float(h1));
}

// ---------------- host ----------------
extern "C" void kernel_launch(void* const* d_in, const int* in_sizes, int n_in,
                              void* d_out, int out_size)
{
    const float* x      = (const float*)d_in[0];
    const float* norm_g = (const float*)d_in[1];
    const float* norm_b = (const float*)d_in[2];
    const float* in_w   = (const float*)d_in[3];
    const float* conv_w = (const float*)d_in[4];
    const float* conv_b = (const float*)d_in[5];
    const float* out_w  = (const float*)d_in[6];
    const float* P[2][9];
    for (int p = 0; p < 2; p++)
        for (int i = 0; i < 9; i++)
            P[p][i] = (const float*)d_in[7 + p * 9 + i];
    // P[p]: 0 in_w, 1 conv_w, 2 conv_b, 3 xp_w, 4 dt_w, 5 dt_b, 6 Alog, 7 D, 8 out_w

    cudaFuncSetAttribute(gemm5<0>, cudaFuncAttributeMaxDynamicSharedMemorySize, SM_TOT);
    cudaFuncSetAttribute(gemm5<1>, cudaFuncAttributeMaxDynamicSharedMemorySize, SM_TOT);
    cudaFuncSetAttribute(gemm5<2>, cudaFuncAttributeMaxDynamicSharedMemorySize, SM_TOT);
    cudaFuncSetAttribute(gemm5<3>, cudaFuncAttributeMaxDynamicSharedMemorySize, SM_TOT);

    float *xp, *xz, *xma, *xdbl, *dtb, *mo;
    bf16 *xnh, *xnl, *xah, *xal, *xmh, *xml, *xdh, *xdl, *ygh, *ygl, *ymh, *yml, *wh, *wl;
    cudaGetSymbolAddress((void**)&xp,   g_xp);
    cudaGetSymbolAddress((void**)&xz,   g_xz);
    cudaGetSymbolAddress((void**)&xma,  g_xma);
    cudaGetSymbolAddress((void**)&xdbl, g_xdbl);
    cudaGetSymbolAddress((void**)&dtb,  g_dt);
    cudaGetSymbolAddress((void**)&mo,   g_mo);
    cudaGetSymbolAddress((void**)&xnh,  g_xnh);  cudaGetSymbolAddress((void**)&xnl, g_xnl);
    cudaGetSymbolAddress((void**)&xah,  g_xah);  cudaGetSymbolAddress((void**)&xal, g_xal);
    cudaGetSymbolAddress((void**)&xmh,  g_xmh);  cudaGetSymbolAddress((void**)&xml, g_xml);
    cudaGetSymbolAddress((void**)&xdh,  g_xdh);  cudaGetSymbolAddress((void**)&xdl, g_xdl);
    cudaGetSymbolAddress((void**)&ygh,  g_ygh);  cudaGetSymbolAddress((void**)&ygl, g_ygl);
    cudaGetSymbolAddress((void**)&ymh,  g_ymh);  cudaGetSymbolAddress((void**)&yml, g_yml);
    cudaGetSymbolAddress((void**)&wh,   g_wh);   cudaGetSymbolAddress((void**)&wl,  g_wl);

    const int EW_GRID = NTOK * DI / 256;
    const int MB = NTOK / 128;   // 64 M-blocks

    // LN -> split xn
    ln_kernel<<<NTOK, 128>>>(x, norm_g, norm_b, xnh, xnl);

    // xp = xn @ in_w^T
    split_kernel<<<DI2 * DMODEL / 4 / 256, 256>>>(in_w, wh, wl, DI2 * DMODEL / 4);
    gemm5<0><<<dim3(DI2 / 128, MB), 128, SM_TOT>>>(xnh, xnl, DMODEL, wh, wl,
                                                   xp, DI2, DMODEL, nullptr, nullptr, nullptr);

    // xa = silu(causal dwconv(xp[:, :DI])) -> split only
    conv_silu_kernel<<<EW_GRID, 256>>>(xp, DI2, conv_w, conv_b, nullptr, xah, xal, 0);

    for (int p = 0; p < 2; p++) {
        float* mop = mo + (size_t)p * NTOK * DI;

        // xz = xa @ p_in_w^T
        split_kernel<<<DI2 * DI / 4 / 256, 256>>>(P[p][0], wh, wl, DI2 * DI / 4);
        gemm5<0><<<dim3(DI2 / 128, MB), 128, SM_TOT>>>(xah, xal, DI, wh, wl,
                                                       xz, DI2, DI, nullptr, nullptr, nullptr);
        // xm = silu(dwconv(xz[:, :DI])) -> fp32 (scan u) + split (xdbl GEMM)
        conv_silu_kernel<<<EW_GRID, 256>>>(xz, DI2, P[p][1], P[p][2], xma, xmh, xml, p);
        // xdbl = xm @ xp_w^T -> fp32 + split
        split_kernel<<<XD * DI / 4 / 256, 256>>>(P[p][3], wh, wl, XD * DI / 4);
        gemm5<3><<<dim3(1, MB), 128, SM_TOT>>>(xmh, xml, DI, wh, wl,
                                               xdbl, XD, DI, nullptr, xdh, xdl);
        // dt = softplus(xdbl[:, :64] @ dt_w^T + dt_b)
        split_kernel<<<DI * DTR / 4 / 256, 256>>>(P[p][4], wh, wl, DI * DTR / 4);
        gemm5<1><<<dim3(DI / 128, MB), 128, SM_TOT>>>(xdh, xdl, XD, wh, wl,
                                                      dtb, DI, DTR, P[p][5], nullptr, nullptr);
        // scan + fused y*silu(z) -> split yg
        scan_kernel<<<BN_ * (DI / 16), 256>>>(xma, dtb, xdbl, xz, P[p][6], P[p][7],
                                              ygh, ygl, p);
        // mamba out = yg @ out_w^T -> fp32 mo[p]
        split_kernel<<<DI * DI / 4 / 256, 256>>>(P[p][8], wh, wl, DI * DI / 4);
        gemm5<0><<<dim3(DI / 128, MB), 128, SM_TOT>>>(ygh, ygl, DI, wh, wl,
                                                      mop, DI, DI, nullptr, nullptr, nullptr);
    }

    // ym = [yf*g, yb*g] -> split
    ymix_kernel<<<EW_GRID, 256>>>(mo, mo + (size_t)NTOK * DI, xp, ymh, yml);

    // out = ym @ out_w^T + x
    split_kernel<<<DMODEL * DI2 / 4 / 256, 256>>>(out_w, wh, wl, DMODEL * DI2 / 4);
    gemm5<2><<<dim3(DMODEL / 128, MB), 128, SM_TOT>>>(ymh, yml, DI2, wh, wl,
                                                      (float*)d_out, DMODEL, DI2, x,
                                                      nullptr, nullptr);
}